// round 16
// baseline (speedup 1.0000x reference)
#include <cuda_runtime.h>
#include <cstdint>

#define FILLV (-1000.0f)
#define NEG_BIG (-3.0e38f)

// Per-batch scratch (allocation-free rule: __device__ globals).
__device__ float g_total[512];
__device__ float g_real[512];

// ---- f32x2 / b64 helpers (validated on sm_103a: add/mul/fma only) --------
__device__ __forceinline__ unsigned long long pk2(float x, float y) {
    unsigned long long r;
    asm("mov.b64 %0, {%1, %2};" : "=l"(r) : "f"(x), "f"(y));
    return r;
}
__device__ __forceinline__ void upk2(unsigned long long a, float& x, float& y) {
    asm("mov.b64 {%0, %1}, %2;" : "=f"(x), "=f"(y) : "l"(a));
}
__device__ __forceinline__ unsigned long long fma2(unsigned long long a,
                                                   unsigned long long b,
                                                   unsigned long long c) {
    unsigned long long r;
    asm("fma.rn.f32x2 %0, %1, %2, %3;" : "=l"(r) : "l"(a), "l"(b), "l"(c));
    return r;
}
__device__ __forceinline__ unsigned long long add2(unsigned long long a,
                                                   unsigned long long b) {
    unsigned long long r;
    asm("add.rn.f32x2 %0, %1, %2;" : "=l"(r) : "l"(a), "l"(b));
    return r;
}

// ---- forward (total path score) kernel -----------------------------------
// 4 batches per CTA, grid = 128, block = 256. ONE barrier per step.
// Thread t: column jj = t >> 1, half h = t & 1 (rows h*64 .. h*64+63).
// The two halves of a column are LANE-ADJACENT -> (c,w) combine is one
// shfl_xor(1), no smem round-trip, no barrier.
// shpv DOUBLE-BUFFERED: publish step s into buf s&1, phase0 reads (s-1)&1
// -> the read->write anti-dependency barrier disappears.
// shpv rows padded ([65] row-pairs): h=0/h=1 read addresses land in different
// banks (528B apart -> bank offset 4) -> conflict-free dual broadcast.
// Deferred reductions (lag-1 contrib/S, lag-2 normalizer M) as in R12/R15,
// now with all 8 warps reducing every batch (parity butterfly, offsets 16..2).
__global__ void __launch_bounds__(256, 1)
crf_forward_kernel(const float* __restrict__ em, const float* __restrict__ trans) {
    __shared__ ulonglong2 shpv[2][4][65];          // [buf][batch][padded row-pair]
    __shared__ __align__(16) float swS[2][4][8];   // [buf][batch][warp] sum(contrib)
    __shared__ __align__(16) float swM[2][4][8];   // [buf][batch][warp] max(pnew)

    const int t    = threadIdx.x;
    const int jj   = t >> 1;
    const int h    = t & 1;
    const int wid  = t >> 5;
    const int lane = t & 31;
    const int b0   = blockIdx.x * 4;
    const int rowbase = h * 64;
    const int g0 = 2 * h, g1 = g0 + 1;   // published batches of this thread
    const int h33 = h * 33;

    // --- T column slice (64 rows), colmax via pair shfl, packed tables ---
    float Tcs[64];
    float tcm = NEG_BIG;
#pragma unroll
    for (int k = 0; k < 64; ++k) {
        float tv = trans[(rowbase + k) * 128 + jj];
        Tcs[k] = tv;
        tcm = fmaxf(tcm, tv);
    }
    const float colmax = fmaxf(tcm, __shfl_xor_sync(0xffffffffu, tcm, 1));

    unsigned long long Tc2[32], Ep[32];
#pragma unroll
    for (int k = 0; k < 32; ++k) {
        Tc2[k] = pk2(Tcs[2 * k], Tcs[2 * k + 1]);
        Ep[k]  = pk2(expf(Tcs[2 * k] - colmax), expf(Tcs[2 * k + 1] - colmax));
    }

    // --- init state into buffer 0 (normalizer P = 0) ---
    const int m   = jj >> 1;
    const int idx = m + (jj >= 64 ? 1 : 0);        // padded row-pair index
    const int lj  = jj & 1;
    {
        float p  = (jj == 126) ? 0.0f : FILLV;
        float vv = (jj == 126) ? 1.0f : 0.0f;
        float* pv0 = (float*)&shpv[0][g0][idx];
        float* pv1 = (float*)&shpv[0][g1][idx];
        pv0[lj] = p;  pv0[2 + lj] = vv;
        pv1[lj] = p;  pv1[2 + lj] = vv;
    }
    float P0 = 0.0f, P1 = 0.0f;          // P_pub of current published v
    float PdP0 = 0.0f, PdP1 = 0.0f;      // P_pub two steps back (for contrib)
    float cP0 = 0.0f, cP1 = 0.0f;        // prev step c
    float wP0 = 0.0f, wP1 = 0.0f;        // prev step w
    float pnP0 = 0.0f, pnP1 = 0.0f;      // prev step pnew
    float Lacc0 = 0.0f, Lacc1 = 0.0f;
    float vkeep0 = 0.0f, vkeep1 = 0.0f;
    __syncthreads();

    const float* embp0 = em + (size_t)(b0 + g0) * 512 * 126;
    const float* embp1 = embp0 + 512 * 126;
    float obs_c0 = (jj < 126) ? embp0[jj] : FILLV;
    float obs_c1 = (jj < 126) ? embp1[jj] : FILLV;

    for (int s = 1; s <= 513; ++s) {
        const int rb = (s - 1) & 1, wb = s & 1;

        // --- deferred reductions for step s-1 (off critical path) ---
        float M0 = 0.0f, M1 = 0.0f;
        if (s > 1) {
            float contrib0 = __expf(PdP0 + colmax - cP0) * wP0;
            float contrib1 = __expf(PdP1 + colmax - cP1) * wP1;
            float sr0 = contrib0, mr0 = pnP0;
            float sr1 = contrib1, mr1 = pnP1;
#pragma unroll
            for (int o = 16; o >= 2; o >>= 1) {     // parity-preserving butterfly
                float a0 = __shfl_xor_sync(0xffffffffu, sr0, o);
                float x0 = __shfl_xor_sync(0xffffffffu, mr0, o);
                float a1 = __shfl_xor_sync(0xffffffffu, sr1, o);
                float x1 = __shfl_xor_sync(0xffffffffu, mr1, o);
                sr0 += a0; mr0 = fmaxf(mr0, x0);
                sr1 += a1; mr1 = fmaxf(mr1, x1);
            }
            if (lane <= 1) {                        // lane0: batches 0,1; lane1: 2,3
                swS[wb][g0][wid] = sr0; swM[wb][g0][wid] = mr0;
                swS[wb][g1][wid] = sr1; swM[wb][g1][wid] = mr1;
            }
            if (s > 2) {
                float4 a = *(const float4*)&swM[rb][g0][0];
                float4 b = *(const float4*)&swM[rb][g0][4];
                M0 = fmaxf(fmaxf(fmaxf(a.x, a.y), fmaxf(a.z, a.w)),
                           fmaxf(fmaxf(b.x, b.y), fmaxf(b.z, b.w)));
                float4 c = *(const float4*)&swM[rb][g1][0];
                float4 d = *(const float4*)&swM[rb][g1][4];
                M1 = fmaxf(fmaxf(fmaxf(c.x, c.y), fmaxf(c.z, c.w)),
                           fmaxf(fmaxf(d.x, d.y), fmaxf(d.z, d.w)));
                float4 e = *(const float4*)&swS[rb][g0][0];
                float4 f = *(const float4*)&swS[rb][g0][4];
                Lacc0 += __logf(((e.x + e.y) + (e.z + e.w)) + ((f.x + f.y) + (f.z + f.w)));
                float4 g = *(const float4*)&swS[rb][g1][0];
                float4 q = *(const float4*)&swS[rb][g1][4];
                Lacc1 += __logf(((g.x + g.y) + (g.z + g.w)) + ((q.x + q.y) + (q.z + q.w)));
            }
        }

        // Prefetch next step's observations (hidden behind phase 0).
        float obs_n0, obs_n1;
        if (s + 1 <= 512) {
            obs_n0 = (jj < 126) ? embp0[(size_t)s * 126 + jj] : FILLV;
            obs_n1 = (jj < 126) ? embp1[(size_t)s * 126 + jj] : FILLV;
        } else {
            float v = (jj == 127) ? 0.0f : FILLV;   // END pseudo-row
            obs_n0 = v; obs_n1 = v;
        }

        // --- phase 0: max-plus + matvec over 64 rows x 4 batches ---
        const ulonglong2* const pA = &shpv[rb][0][h33];
        const ulonglong2* const pB = &shpv[rb][1][h33];
        const ulonglong2* const pC = &shpv[rb][2][h33];
        const ulonglong2* const pD = &shpv[rb][3][h33];
        float cm0A = NEG_BIG, cm1A = NEG_BIG;
        float cm0B = NEG_BIG, cm1B = NEG_BIG;
        float cm0C = NEG_BIG, cm1C = NEG_BIG;
        float cm0D = NEG_BIG, cm1D = NEG_BIG;
        unsigned long long wA = 0ULL, wB = 0ULL, wC = 0ULL, wD = 0ULL;
#pragma unroll
        for (int k = 0; k < 32; ++k) {
            ulonglong2 qA = pA[k];
            ulonglong2 qB = pB[k];
            ulonglong2 qC = pC[k];
            ulonglong2 qD = pD[k];
            float s0, s1;
            unsigned long long u;
            u = add2(qA.x, Tc2[k]); upk2(u, s0, s1);
            cm0A = fmaxf(cm0A, s0); cm1A = fmaxf(cm1A, s1);
            wA = fma2(qA.y, Ep[k], wA);
            u = add2(qB.x, Tc2[k]); upk2(u, s0, s1);
            cm0B = fmaxf(cm0B, s0); cm1B = fmaxf(cm1B, s1);
            wB = fma2(qB.y, Ep[k], wB);
            u = add2(qC.x, Tc2[k]); upk2(u, s0, s1);
            cm0C = fmaxf(cm0C, s0); cm1C = fmaxf(cm1C, s1);
            wC = fma2(qC.y, Ep[k], wC);
            u = add2(qD.x, Tc2[k]); upk2(u, s0, s1);
            cm0D = fmaxf(cm0D, s0); cm1D = fmaxf(cm1D, s1);
            wD = fma2(qD.y, Ep[k], wD);
        }
        // scalar partials per batch
        float cA = fmaxf(cm0A, cm1A), cB = fmaxf(cm0B, cm1B);
        float cC = fmaxf(cm0C, cm1C), cD = fmaxf(cm0D, cm1D);
        float wa0, wa1;
        upk2(wA, wa0, wa1); float wAs = wa0 + wa1;
        upk2(wB, wa0, wa1); float wBs = wa0 + wa1;
        upk2(wC, wa0, wa1); float wCs = wa0 + wa1;
        upk2(wD, wa0, wa1); float wDs = wa0 + wa1;

        // --- pair exchange: send partner the partials for THEIR batches ---
        float myc0 = h ? cC : cA,  myc1 = h ? cD : cB;
        float myw0 = h ? wCs : wAs, myw1 = h ? wDs : wBs;
        float sc0 = h ? cA : cC,  sc1 = h ? cB : cD;
        float sw0 = h ? wAs : wCs, sw1 = h ? wBs : wDs;
        float rc0 = __shfl_xor_sync(0xffffffffu, sc0, 1);
        float rc1 = __shfl_xor_sync(0xffffffffu, sc1, 1);
        float rw0 = __shfl_xor_sync(0xffffffffu, sw0, 1);
        float rw1 = __shfl_xor_sync(0xffffffffu, sw1, 1);
        float c0 = fmaxf(myc0, rc0), w0f = myw0 + rw0;
        float c1 = fmaxf(myc1, rc1), w1f = myw1 + rw1;

        // --- publish new state for owned batches (buffer wb) ---
        float pnew0 = obs_c0 + c0;
        float pnew1 = obs_c1 + c1;
        float v0 = __expf(pnew0 - M0);
        float v1 = __expf(pnew1 - M1);
        vkeep0 = v0; vkeep1 = v1;
        {
            float* pv0 = (float*)&shpv[wb][g0][idx];
            float* pv1 = (float*)&shpv[wb][g1][idx];
            pv0[lj] = pnew0;  pv0[2 + lj] = v0;
            pv1[lj] = pnew1;  pv1[2 + lj] = v1;
        }

        // roll deferred state
        PdP0 = P0; PdP1 = P1;
        P0 = M0;  P1 = M1;
        cP0 = c0; cP1 = c1;
        wP0 = w0f; wP1 = w1f;
        pnP0 = pnew0; pnP1 = pnew1;

        __syncthreads();                            // the ONLY barrier per step
        obs_c0 = obs_n0;
        obs_c1 = obs_n1;
    }

    // --- epilogue ---
    {
        // Lacc += log S(512): totals written during step 513 into buffer 1
        float4 e = *(const float4*)&swS[1][g0][0];
        float4 f = *(const float4*)&swS[1][g0][4];
        Lacc0 += __logf(((e.x + e.y) + (e.z + e.w)) + ((f.x + f.y) + (f.z + f.w)));
        float4 g = *(const float4*)&swS[1][g1][0];
        float4 q = *(const float4*)&swS[1][g1][4];
        Lacc1 += __logf(((g.x + g.y) + (g.z + g.w)) + ((q.x + q.y) + (q.z + q.w)));

        // contrib(513) + final sum of v(513)
        float contrib0 = __expf(PdP0 + colmax - cP0) * wP0;
        float contrib1 = __expf(PdP1 + colmax - cP1) * wP1;
        float sr0 = contrib0, sv0 = vkeep0;
        float sr1 = contrib1, sv1 = vkeep1;
#pragma unroll
        for (int o = 16; o >= 2; o >>= 1) {
            sr0 += __shfl_xor_sync(0xffffffffu, sr0, o);
            sv0 += __shfl_xor_sync(0xffffffffu, sv0, o);
            sr1 += __shfl_xor_sync(0xffffffffu, sr1, o);
            sv1 += __shfl_xor_sync(0xffffffffu, sv1, o);
        }
        if (lane <= 1) {
            swS[0][g0][wid] = sr0; swM[0][g0][wid] = sv0;   // swM reused: sum(v)
            swS[0][g1][wid] = sr1; swM[0][g1][wid] = sv1;
        }
    }
    __syncthreads();
    if (t < 2) {     // t=0 -> batches 0,1 ; t=1 -> batches 2,3 (h matches)
        float S0 = 0.0f, S1 = 0.0f, Sv0 = 0.0f, Sv1 = 0.0f;
#pragma unroll
        for (int k = 0; k < 8; ++k) {
            S0 += swS[0][g0][k];  Sv0 += swM[0][g0][k];
            S1 += swS[0][g1][k];  Sv1 += swM[0][g1][k];
        }
        g_total[b0 + g0] = P0 + logf(Sv0) + Lacc0 + logf(S0);
        g_total[b0 + g1] = P1 + logf(Sv1) + Lacc1 + logf(S1);
    }
}

// ---- gold-path score kernel ----------------------------------------------
__global__ void crf_real_kernel(const float* __restrict__ em,
                                const int* __restrict__ labels,
                                const float* __restrict__ trans) {
    const int b = blockIdx.x;
    const int t = threadIdx.x;   // 128 threads
    __shared__ float sw[4];
    const int* lb = labels + b * 512;
    const float* emb = em + (size_t)b * 512 * 126;

    float acc = 0.0f;
    for (int tt = t; tt < 512; tt += 128) {
        int l0 = lb[tt];
        acc += emb[tt * 126 + l0];
        int l1 = (tt < 511) ? lb[tt + 1] : 127;     // END = L+1 = 127
        acc += trans[l0 * 128 + l1];
    }
    if (t == 0) acc += trans[126 * 128 + lb[0]];     // START = L = 126

#pragma unroll
    for (int o = 16; o; o >>= 1) acc += __shfl_xor_sync(0xffffffffu, acc, o);
    if ((t & 31) == 0) sw[t >> 5] = acc;
    __syncthreads();
    if (t == 0) g_real[b] = (sw[0] + sw[1]) + (sw[2] + sw[3]);
}

// ---- fixed-order final reduction (deterministic) -------------------------
__global__ void crf_reduce_kernel(float* __restrict__ out) {
    const int t = threadIdx.x;   // 512 threads
    __shared__ float sw[16];
    float d = g_total[t] - g_real[t];
#pragma unroll
    for (int o = 16; o; o >>= 1) d += __shfl_xor_sync(0xffffffffu, d, o);
    if ((t & 31) == 0) sw[t >> 5] = d;
    __syncthreads();
    if (t == 0) {
        float s = 0.0f;
#pragma unroll
        for (int w = 0; w < 16; ++w) s += sw[w];
        out[0] = s;
    }
}

extern "C" void kernel_launch(void* const* d_in, const int* in_sizes, int n_in,
                              void* d_out, int out_size) {
    const float* em     = (const float*)d_in[0];   // [512, 512, 126] f32
    const int*   labels = (const int*)d_in[1];     // [512, 512] i32
    const float* trans  = (const float*)d_in[2];   // [128, 128] f32

    crf_forward_kernel<<<128, 256>>>(em, trans);
    crf_real_kernel<<<512, 128>>>(em, labels, trans);
    crf_reduce_kernel<<<1, 512>>>((float*)d_out);
}

// round 17
// speedup vs baseline: 1.2392x; 1.2392x over previous
#include <cuda_runtime.h>
#include <cstdint>

#define FILLV (-1000.0f)
#define NEG_BIG (-3.0e38f)

// Per-batch scratch (allocation-free rule: __device__ globals).
__device__ float g_total[512];
__device__ float g_real[512];

// ---- f32x2 / b64 helpers (validated on sm_103a: add/mul/fma only) --------
__device__ __forceinline__ unsigned long long pk2(float x, float y) {
    unsigned long long r;
    asm("mov.b64 %0, {%1, %2};" : "=l"(r) : "f"(x), "f"(y));
    return r;
}
__device__ __forceinline__ void upk2(unsigned long long a, float& x, float& y) {
    asm("mov.b64 {%0, %1}, %2;" : "=f"(x), "=f"(y) : "l"(a));
}
__device__ __forceinline__ unsigned long long fma2(unsigned long long a,
                                                   unsigned long long b,
                                                   unsigned long long c) {
    unsigned long long r;
    asm("fma.rn.f32x2 %0, %1, %2, %3;" : "=l"(r) : "l"(a), "l"(b), "l"(c));
    return r;
}
__device__ __forceinline__ unsigned long long add2(unsigned long long a,
                                                   unsigned long long b) {
    unsigned long long r;
    asm("add.rn.f32x2 %0, %1, %2;" : "=l"(r) : "l"(a), "l"(b));
    return r;
}

// ---- forward (total path score) kernel -----------------------------------
// 4 batches per CTA, grid = 128, block = 512 (4 warps/SMSP).
// Thread t: column jj = t & 127, quarter q = t >> 7 (rows q*32 .. q*32+31).
// Quarter q OWNS batch q end-to-end (obs, phaseC, publish, deferred).
// Register tables: Tc2[16] + Ep[16] = 64 regs (halved vs R15 -> scheduling
// headroom). Phase-0 shpv reads stay single-address warp broadcasts.
// Deferral exactly as R15 (759.8us champion): contrib exp + shfl reduction
// for step s-1 at the top of step s; swS/swM single-buffered (write before
// phase-0 barrier, read after it). Two barriers per step.
__global__ void __launch_bounds__(512, 1)
crf_forward_kernel(const float* __restrict__ em, const float* __restrict__ trans) {
    __shared__ ulonglong2 shpv[4][64];    // per batch: {p[2m],p[2m+1] | v[2m],v[2m+1]}
    __shared__ float2 spcw[4][512];       // per batch: per-thread (cm, w) at [g][t]
    __shared__ float scol[128];           // colmax of transitions
    __shared__ __align__(16) float swS[4][4];   // [batch][warp-of-quarter] sum(contrib)
    __shared__ __align__(16) float swM[4][4];   // [batch][warp-of-quarter] max(pnew)

    const int t    = threadIdx.x;
    const int jj   = t & 127;
    const int q    = t >> 7;              // quarter; owns batch q
    const int wi   = (t >> 5) & 3;        // warp index within quarter
    const int lane = t & 31;
    const int b0   = blockIdx.x * 4;
    const int rowbase = q * 32;

    // --- T column slice (32 rows), colmax across quarters, packed tables ---
    float Tcs[32];
    float tcm = NEG_BIG;
#pragma unroll
    for (int k = 0; k < 32; ++k) {
        float tv = trans[(rowbase + k) * 128 + jj];
        Tcs[k] = tv;
        tcm = fmaxf(tcm, tv);
    }
    ((float*)spcw)[t] = tcm;
    __syncthreads();
    if (t < 128) {
        scol[t] = fmaxf(fmaxf(((float*)spcw)[t],       ((float*)spcw)[t + 128]),
                        fmaxf(((float*)spcw)[t + 256], ((float*)spcw)[t + 384]));
    }
    __syncthreads();
    const float colmax = scol[jj];

    unsigned long long Tc2[16], Ep[16];
#pragma unroll
    for (int k = 0; k < 16; ++k) {
        Tc2[k] = pk2(Tcs[2 * k], Tcs[2 * k + 1]);
        Ep[k]  = pk2(expf(Tcs[2 * k] - colmax), expf(Tcs[2 * k + 1] - colmax));
    }

    // --- init state: quarter q initializes batch q (normalizer P = 0) ---
    const int m  = jj >> 1;
    const int lj = jj & 1;
    {
        float p  = (jj == 126) ? 0.0f : FILLV;
        float vv = (jj == 126) ? 1.0f : 0.0f;
        float* pvf = (float*)(shpv[q]);
        pvf[m * 4 + lj]     = p;
        pvf[m * 4 + 2 + lj] = vv;
    }
    float P = 0.0f;          // normalizer of currently-published v
    float PdP = 0.0f;        // normalizer two steps back (for deferred contrib)
    float cP = 0.0f;         // prev step c
    float wP = 0.0f;         // prev step w
    float pnP = 0.0f;        // prev step pnew
    float Lacc = 0.0f;
    float vkeep = 0.0f;
    __syncthreads();

    const float* embp = em + (size_t)(b0 + q) * 512 * 126;
    float obs_c = (jj < 126) ? embp[jj] : FILLV;

    const ulonglong2* const pvA = shpv[0] + q * 16;
    const ulonglong2* const pvB = shpv[1] + q * 16;
    const ulonglong2* const pvC = shpv[2] + q * 16;
    const ulonglong2* const pvD = shpv[3] + q * 16;

    for (int s = 1; s <= 513; ++s) {
        // --- deferred reduction for step s-1 (off critical path) ---
        if (s > 1) {
            float contrib = __expf(PdP + colmax - cP) * wP;
            float sr = contrib, mr = pnP;
#pragma unroll
            for (int o = 16; o; o >>= 1) {
                float a0 = __shfl_xor_sync(0xffffffffu, sr, o);
                float x0 = __shfl_xor_sync(0xffffffffu, mr, o);
                sr += a0; mr = fmaxf(mr, x0);
            }
            if (lane == 0) { swS[q][wi] = sr; swM[q][wi] = mr; }
        }

        // Prefetch next step's observation (owned batch; hidden behind phase 0).
        float obs_n;
        if (s + 1 <= 512) {
            obs_n = (jj < 126) ? embp[(size_t)s * 126 + jj] : FILLV;
        } else {
            obs_n = (jj == 127) ? 0.0f : FILLV;   // END pseudo-row
        }

        // --- phase 0: max-plus + matvec over 32 rows x 4 batches ---
        float cm0A = NEG_BIG, cm1A = NEG_BIG;
        float cm0B = NEG_BIG, cm1B = NEG_BIG;
        float cm0C = NEG_BIG, cm1C = NEG_BIG;
        float cm0D = NEG_BIG, cm1D = NEG_BIG;
        unsigned long long wA = 0ULL, wB = 0ULL, wC = 0ULL, wD = 0ULL;
#pragma unroll
        for (int k = 0; k < 16; ++k) {
            ulonglong2 qA = pvA[k];
            ulonglong2 qB = pvB[k];
            ulonglong2 qC = pvC[k];
            ulonglong2 qD = pvD[k];
            float s0, s1;
            unsigned long long u;
            u = add2(qA.x, Tc2[k]); upk2(u, s0, s1);
            cm0A = fmaxf(cm0A, s0); cm1A = fmaxf(cm1A, s1);
            wA = fma2(qA.y, Ep[k], wA);
            u = add2(qB.x, Tc2[k]); upk2(u, s0, s1);
            cm0B = fmaxf(cm0B, s0); cm1B = fmaxf(cm1B, s1);
            wB = fma2(qB.y, Ep[k], wB);
            u = add2(qC.x, Tc2[k]); upk2(u, s0, s1);
            cm0C = fmaxf(cm0C, s0); cm1C = fmaxf(cm1C, s1);
            wC = fma2(qC.y, Ep[k], wC);
            u = add2(qD.x, Tc2[k]); upk2(u, s0, s1);
            cm0D = fmaxf(cm0D, s0); cm1D = fmaxf(cm1D, s1);
            wD = fma2(qD.y, Ep[k], wD);
        }
        {
            float w0, w1;
            upk2(wA, w0, w1); spcw[0][t] = make_float2(fmaxf(cm0A, cm1A), w0 + w1);
            upk2(wB, w0, w1); spcw[1][t] = make_float2(fmaxf(cm0B, cm1B), w0 + w1);
            upk2(wC, w0, w1); spcw[2][t] = make_float2(fmaxf(cm0C, cm1C), w0 + w1);
            upk2(wD, w0, w1); spcw[3][t] = make_float2(fmaxf(cm0D, cm1D), w0 + w1);
        }
        __syncthreads();

        // --- phaseC: owned batch q only ---
        float2 z0 = spcw[q][jj];
        float2 z1 = spcw[q][jj + 128];
        float2 z2 = spcw[q][jj + 256];
        float2 z3 = spcw[q][jj + 384];
        float c = fmaxf(fmaxf(z0.x, z1.x), fmaxf(z2.x, z3.x));
        float w = (z0.y + z1.y) + (z2.y + z3.y);
        float pnew = obs_c + c;

        float M;
        if (s > 1) {
            float4 mv = *reinterpret_cast<const float4*>(&swM[q][0]);
            M = fmaxf(fmaxf(mv.x, mv.y), fmaxf(mv.z, mv.w));
        } else {
            M = 0.0f;
        }

        float v = __expf(pnew - M);
        vkeep = v;
        {
            float* pvf = (float*)(shpv[q]);
            pvf[m * 4 + lj]     = pnew;
            pvf[m * 4 + 2 + lj] = v;
        }

        // Off-path accumulation: Lacc += log(S_{s-1})
        if (s > 1) {
            float4 sv = *reinterpret_cast<const float4*>(&swS[q][0]);
            Lacc += __logf((sv.x + sv.y) + (sv.z + sv.w));
        }

        // Roll deferred state.
        PdP = P;
        P = M;
        cP = c;
        wP = w;
        pnP = pnew;

        __syncthreads();
        obs_c = obs_n;
    }

    // --- epilogue: flush step-513 deferred contrib + final log-sum-exp ---
    {
        float contrib = __expf(PdP + colmax - cP) * wP;
        float sr = contrib, sv = vkeep;
#pragma unroll
        for (int o = 16; o; o >>= 1) {
            sr += __shfl_xor_sync(0xffffffffu, sr, o);
            sv += __shfl_xor_sync(0xffffffffu, sv, o);
        }
        if (lane == 0) {
            swS[q][wi] = sr;  swM[q][wi] = sv;   // swM reused as sum(v)
        }
    }
    __syncthreads();
    if (jj == 0) {
        float4 sS = *reinterpret_cast<const float4*>(&swS[q][0]);
        float4 sV = *reinterpret_cast<const float4*>(&swM[q][0]);
        float S  = (sS.x + sS.y) + (sS.z + sS.w);
        float Sv = (sV.x + sV.y) + (sV.z + sV.w);
        g_total[b0 + q] = P + logf(Sv) + Lacc + logf(S);
    }
}

// ---- gold-path score kernel ----------------------------------------------
__global__ void crf_real_kernel(const float* __restrict__ em,
                                const int* __restrict__ labels,
                                const float* __restrict__ trans) {
    const int b = blockIdx.x;
    const int t = threadIdx.x;   // 128 threads
    __shared__ float sw[4];
    const int* lb = labels + b * 512;
    const float* emb = em + (size_t)b * 512 * 126;

    float acc = 0.0f;
    for (int tt = t; tt < 512; tt += 128) {
        int l0 = lb[tt];
        acc += emb[tt * 126 + l0];
        int l1 = (tt < 511) ? lb[tt + 1] : 127;     // END = L+1 = 127
        acc += trans[l0 * 128 + l1];
    }
    if (t == 0) acc += trans[126 * 128 + lb[0]];     // START = L = 126

#pragma unroll
    for (int o = 16; o; o >>= 1) acc += __shfl_xor_sync(0xffffffffu, acc, o);
    if ((t & 31) == 0) sw[t >> 5] = acc;
    __syncthreads();
    if (t == 0) g_real[b] = (sw[0] + sw[1]) + (sw[2] + sw[3]);
}

// ---- fixed-order final reduction (deterministic) -------------------------
__global__ void crf_reduce_kernel(float* __restrict__ out) {
    const int t = threadIdx.x;   // 512 threads
    __shared__ float sw[16];
    float d = g_total[t] - g_real[t];
#pragma unroll
    for (int o = 16; o; o >>= 1) d += __shfl_xor_sync(0xffffffffu, d, o);
    if ((t & 31) == 0) sw[t >> 5] = d;
    __syncthreads();
    if (t == 0) {
        float s = 0.0f;
#pragma unroll
        for (int w = 0; w < 16; ++w) s += sw[w];
        out[0] = s;
    }
}

extern "C" void kernel_launch(void* const* d_in, const int* in_sizes, int n_in,
                              void* d_out, int out_size) {
    const float* em     = (const float*)d_in[0];   // [512, 512, 126] f32
    const int*   labels = (const int*)d_in[1];     // [512, 512] i32
    const float* trans  = (const float*)d_in[2];   // [128, 128] f32

    crf_forward_kernel<<<128, 512>>>(em, trans);
    crf_real_kernel<<<512, 128>>>(em, labels, trans);
    crf_reduce_kernel<<<1, 512>>>((float*)d_out);
}